// round 3
// baseline (speedup 1.0000x reference)
#include <cuda_runtime.h>
#include <math.h>

#define S_ 256
#define B_ 512
#define H_ 256
#define H3 768
#define VOCAB_ 32000
#define NSTACK 2
#define SSIZE 64
#define ELEM 64

// ---------------- device scratch (static, no allocation) ----------------
__device__ float g_EMB_GI[VOCAB_ * H3];       // emb @ W_ih^T + b_ih
__device__ float g_WihT[H_ * H3];             // [k][n]
__device__ float g_WhhT[H_ * H3];             // [k][n]
__device__ float g_WstkT[H_ * (NSTACK * ELEM)];
__device__ float g_Wa1T[H_ * H_];
__device__ float g_h[2][B_ * H_];             // hidden ping-pong
__device__ float g_PV[2][B_ * NSTACK * ELEM]; // push_vals ping-pong
__device__ float g_P[2][B_ * NSTACK * 3];     // act probs ping-pong
__device__ float g_spart[2][S_ * B_];         // attention score partials (per n-tile)

__device__ __forceinline__ float sigmoidf_(float x) { return 1.f / (1.f + expf(-x)); }

// ---------------- packed f32x2 helpers ----------------
__device__ __forceinline__ unsigned long long pack2(float x) {
    unsigned long long d;
    unsigned int u = __float_as_uint(x);
    asm("mov.b64 %0, {%1, %1};" : "=l"(d) : "r"(u));
    return d;
}
__device__ __forceinline__ void fma2(unsigned long long& d, unsigned long long a,
                                     unsigned long long b) {
    asm("fma.rn.f32x2 %0, %1, %2, %0;" : "+l"(d) : "l"(a), "l"(b));
}
__device__ __forceinline__ float2 unpack2(unsigned long long v) {
    unsigned int lo, hi;
    asm("mov.b64 {%0, %1}, %2;" : "=r"(lo), "=r"(hi) : "l"(v));
    return make_float2(__uint_as_float(lo), __uint_as_float(hi));
}

// ---------------- prep: all transposes + h0 + stacks init, ONE launch ----------------
__global__ void prep_k(const float* __restrict__ W_ih, const float* __restrict__ W_hh,
                       const float* __restrict__ W_stk, const float* __restrict__ Wa1,
                       const float* __restrict__ empty_elem, float* __restrict__ stacks) {
    int idx = blockIdx.x * blockDim.x + threadIdx.x;
    if (idx < H3 * H_) {                     // dst[c*H3 + r] layout via idx walk
        int r = idx % H3, c = idx / H3;
        g_WihT[idx] = W_ih[r * H_ + c];
        g_WhhT[idx] = W_hh[r * H_ + c];
    }
    if (idx < (NSTACK * ELEM) * H_) {
        int r = idx % (NSTACK * ELEM), c = idx / (NSTACK * ELEM);
        g_WstkT[idx] = W_stk[r * H_ + c];
    }
    if (idx < H_ * H_) {
        int r = idx % H_, c = idx / H_;
        g_Wa1T[idx] = Wa1[r * H_ + c];
    }
    if (idx < B_ * H_) g_h[0][idx] = 0.f;
    if (idx < B_ * NSTACK * SSIZE * ELEM) stacks[idx] = empty_elem[idx & (ELEM - 1)];
}

// ---------------- 128x128x16 SGEMM with f32x2 ----------------
// SCORE=false: C = A@B + bias (used for EMB_GI)
// SCORE=true : g_spart[blockIdx.x][m] = sum_n tanh(A@B + bias)[m][n] * Wa2[n]; C unused
template <bool SCORE>
__global__ void __launch_bounds__(256) sgemm128_k(
    const float* __restrict__ A, const float* __restrict__ Bm,
    const float* __restrict__ bias, float* __restrict__ C,
    const float* __restrict__ Wa2,
    int M, int N, int K)
{
    __shared__ __align__(16) float As[16][128];   // [k][m]
    __shared__ __align__(16) float Bs[16][128];   // [k][n]
    int tid = threadIdx.x;
    int m0 = blockIdx.y * 128, n0 = blockIdx.x * 128;
    int tx = tid & 15, ty = tid >> 4;

    unsigned long long acc[2][2][4][2];           // [ichunk][jchunk][i][jpair]
#pragma unroll
    for (int a = 0; a < 2; a++)
#pragma unroll
        for (int b = 0; b < 2; b++)
#pragma unroll
            for (int c = 0; c < 4; c++) { acc[a][b][c][0] = 0ull; acc[a][b][c][1] = 0ull; }

    for (int k0 = 0; k0 < K; k0 += 16) {
#pragma unroll
        for (int i = 0; i < 2; i++) {
            int f = tid * 2 + i;
            int arow = f >> 2, aq = (f & 3) * 4;
            float4 v = *(const float4*)&A[(size_t)(m0 + arow) * K + k0 + aq];
            As[aq + 0][arow] = v.x; As[aq + 1][arow] = v.y;
            As[aq + 2][arow] = v.z; As[aq + 3][arow] = v.w;
            int brow = f >> 5, bc = (f & 31) * 4;
            *(float4*)&Bs[brow][bc] = *(const float4*)&Bm[(size_t)(k0 + brow) * N + n0 + bc];
        }
        __syncthreads();
#pragma unroll
        for (int kk = 0; kk < 16; kk++) {
            float4 a0 = *(float4*)&As[kk][ty * 4];
            float4 a1 = *(float4*)&As[kk][ty * 4 + 64];
            unsigned long long ap[2][4];
            ap[0][0] = pack2(a0.x); ap[0][1] = pack2(a0.y);
            ap[0][2] = pack2(a0.z); ap[0][3] = pack2(a0.w);
            ap[1][0] = pack2(a1.x); ap[1][1] = pack2(a1.y);
            ap[1][2] = pack2(a1.z); ap[1][3] = pack2(a1.w);
            ulonglong2 b0 = *(ulonglong2*)&Bs[kk][tx * 4];
            ulonglong2 b1 = *(ulonglong2*)&Bs[kk][tx * 4 + 64];
#pragma unroll
            for (int ic = 0; ic < 2; ic++)
#pragma unroll
                for (int i = 0; i < 4; i++) {
                    fma2(acc[ic][0][i][0], ap[ic][i], b0.x);
                    fma2(acc[ic][0][i][1], ap[ic][i], b0.y);
                    fma2(acc[ic][1][i][0], ap[ic][i], b1.x);
                    fma2(acc[ic][1][i][1], ap[ic][i], b1.y);
                }
        }
        __syncthreads();
    }

    if (!SCORE) {
#pragma unroll
        for (int ic = 0; ic < 2; ic++)
#pragma unroll
            for (int i = 0; i < 4; i++) {
                int m = m0 + ic * 64 + ty * 4 + i;
#pragma unroll
                for (int jc = 0; jc < 2; jc++) {
                    int n = n0 + jc * 64 + tx * 4;
                    float2 p0 = unpack2(acc[ic][jc][i][0]);
                    float2 p1 = unpack2(acc[ic][jc][i][1]);
                    float4 o;
                    o.x = p0.x + bias[n + 0];
                    o.y = p0.y + bias[n + 1];
                    o.z = p1.x + bias[n + 2];
                    o.w = p1.y + bias[n + 3];
                    *(float4*)&C[(size_t)m * N + n] = o;
                }
            }
    } else {
        float4 bb[2], ww[2];
#pragma unroll
        for (int jc = 0; jc < 2; jc++) {
            int n = n0 + jc * 64 + tx * 4;
            bb[jc] = *(const float4*)&bias[n];
            ww[jc] = *(const float4*)&Wa2[n];
        }
#pragma unroll
        for (int ic = 0; ic < 2; ic++)
#pragma unroll
            for (int i = 0; i < 4; i++) {
                float p = 0.f;
#pragma unroll
                for (int jc = 0; jc < 2; jc++) {
                    float2 p0 = unpack2(acc[ic][jc][i][0]);
                    float2 p1 = unpack2(acc[ic][jc][i][1]);
                    p += tanhf(p0.x + bb[jc].x) * ww[jc].x;
                    p += tanhf(p0.y + bb[jc].y) * ww[jc].y;
                    p += tanhf(p1.x + bb[jc].z) * ww[jc].z;
                    p += tanhf(p1.y + bb[jc].w) * ww[jc].w;
                }
#pragma unroll
                for (int off = 8; off > 0; off >>= 1)
                    p += __shfl_xor_sync(0xffffffffu, p, off);
                if (tx == 0) {
                    int m = m0 + ic * 64 + ty * 4 + i;
                    g_spart[blockIdx.x][m] = p;
                }
            }
    }
}

// ---------------- fused per-step kernel ----------------
// blocks [0,128):    GRU  16 batch rows x 64 j cols x 3 gates, f32x2
// blocks [128,160):  AUX  PV_s = tanh(h_s @ W_stk^T + b_stk)
// blocks [160,192):  ACT  P_s = softmax(h_s @ W_act^T + b_act)
// blocks [192,448):  STACK update for step s-1 (2 stacks per block)
#define GRU_BLOCKS 128
#define AUX_BLOCKS 32
#define ACT_BLOCKS 32
#define STACK_BASE (GRU_BLOCKS + AUX_BLOCKS + ACT_BLOCKS)
#define STEP_BLOCKS (STACK_BASE + B_ / 2)     // 448

__global__ void __launch_bounds__(256) step_kernel(
    int s,
    const int* __restrict__ tokens,
    const float* __restrict__ b_ih,
    const float* __restrict__ b_hh,
    const float* __restrict__ W_act,
    const float* __restrict__ b_act,
    const float* __restrict__ b_stk,
    const float* __restrict__ empty_elem,
    float* __restrict__ outputs,
    float* __restrict__ stacks)
{
    __shared__ __align__(16) float sm[6704];
    int tid = threadIdx.x;
    int blk = blockIdx.x;

    if (blk < GRU_BLOCKS) {
        if (s >= S_) return;
        const float* hin = g_h[s & 1];
        float* hout = g_h[(s + 1) & 1];
        int mt = blk >> 2, jt = blk & 3;
        int b0 = mt * 16, j0 = jt * 64;
        float* As = sm;                 // [16][33]
        float* Bs = sm + 16 * 33;       // [3][32][64]
        int tx = tid & 15, bl = tid >> 4;
        int jq = tx * 4;
        unsigned long long acc[3][2] = {{0ull,0ull},{0ull,0ull},{0ull,0ull}};

        for (int k0 = 0; k0 < H_; k0 += 32) {
            {   // A tile: 16 rows x 32 k, coalesced float2 loads
                float2 v = *(const float2*)&hin[(b0 + bl) * H_ + k0 + tx * 2];
                As[bl * 33 + tx * 2 + 0] = v.x;
                As[bl * 33 + tx * 2 + 1] = v.y;
            }
            {   // B tile: 3 gates x 32 k x 64 j
                int r = tid >> 3, c8 = (tid & 7) * 8;
                const float* src = &g_WhhT[(size_t)(k0 + r) * H3 + j0 + c8];
#pragma unroll
                for (int g = 0; g < 3; g++) {
                    *(float4*)&Bs[(g * 32 + r) * 64 + c8]     = *(const float4*)(src + g * H_);
                    *(float4*)&Bs[(g * 32 + r) * 64 + c8 + 4] = *(const float4*)(src + g * H_ + 4);
                }
            }
            __syncthreads();
#pragma unroll
            for (int kk = 0; kk < 32; kk++) {
                unsigned long long ap = pack2(As[bl * 33 + kk]);
#pragma unroll
                for (int g = 0; g < 3; g++) {
                    ulonglong2 bv = *(ulonglong2*)&Bs[(g * 32 + kk) * 64 + jq];
                    fma2(acc[g][0], ap, bv.x);
                    fma2(acc[g][1], ap, bv.y);
                }
            }
            __syncthreads();
        }

        // epilogue: gates for 4 consecutive j
        int b = b0 + bl;
        int j = j0 + jq;
        int tok = tokens[s * B_ + b];
        const float* gi = (tok == 0) ? b_ih : (g_EMB_GI + (size_t)tok * H3);
        float4 gir = *(const float4*)&gi[j];
        float4 giz = *(const float4*)&gi[H_ + j];
        float4 gin = *(const float4*)&gi[2 * H_ + j];
        float4 bhr = *(const float4*)&b_hh[j];
        float4 bhz = *(const float4*)&b_hh[H_ + j];
        float4 bhn = *(const float4*)&b_hh[2 * H_ + j];
        float2 r01 = unpack2(acc[0][0]), r23 = unpack2(acc[0][1]);
        float2 z01 = unpack2(acc[1][0]), z23 = unpack2(acc[1][1]);
        float2 n01 = unpack2(acc[2][0]), n23 = unpack2(acc[2][1]);
        float4 hp = *(const float4*)&hin[b * H_ + j];
        float4 o;
        {
            float r = sigmoidf_(gir.x + r01.x + bhr.x);
            float z = sigmoidf_(giz.x + z01.x + bhz.x);
            float n = tanhf(gin.x + r * (n01.x + bhn.x));
            o.x = (1.f - z) * n + z * hp.x;
        }
        {
            float r = sigmoidf_(gir.y + r01.y + bhr.y);
            float z = sigmoidf_(giz.y + z01.y + bhz.y);
            float n = tanhf(gin.y + r * (n01.y + bhn.y));
            o.y = (1.f - z) * n + z * hp.y;
        }
        {
            float r = sigmoidf_(gir.z + r23.x + bhr.z);
            float z = sigmoidf_(giz.z + z23.x + bhz.z);
            float n = tanhf(gin.z + r * (n23.x + bhn.z));
            o.z = (1.f - z) * n + z * hp.z;
        }
        {
            float r = sigmoidf_(gir.w + r23.y + bhr.w);
            float z = sigmoidf_(giz.w + z23.y + bhz.w);
            float n = tanhf(gin.w + r * (n23.y + bhn.w));
            o.w = (1.f - z) * n + z * hp.w;
        }
        *(float4*)&hout[b * H_ + j] = o;
        *(float4*)&outputs[((size_t)s * B_ + b) * H_ + j] = o;
        return;
    }

    if (blk < GRU_BLOCKS + AUX_BLOCKS) {
        if (s >= S_) return;
        int ab = blk - GRU_BLOCKS;
        const float* hin = g_h[s & 1];
        float* pvout = g_PV[s & 1];
        int b0 = (ab >> 1) * 32;
        int c0 = (ab & 1) * 64;
        float* As = sm;          // [32][17]
        float* Bs = sm + 544;    // [16][64]
        int tx = tid & 15, ty = tid >> 4;
        unsigned long long acc[2][2] = {{0ull,0ull},{0ull,0ull}};
        for (int k0 = 0; k0 < H_; k0 += 16) {
            {
                int m = tid >> 3, q = (tid & 7) * 2;
                float2 v = *(const float2*)&hin[(b0 + m) * H_ + k0 + q];
                As[m * 17 + q] = v.x; As[m * 17 + q + 1] = v.y;
            }
            {
                int k = tid >> 4, nq = (tid & 15) * 4;
                *(float4*)&Bs[k * 64 + nq] =
                    *(const float4*)&g_WstkT[(k0 + k) * (NSTACK * ELEM) + c0 + nq];
            }
            __syncthreads();
#pragma unroll
            for (int kk = 0; kk < 16; kk++) {
                unsigned long long a0 = pack2(As[(ty * 2) * 17 + kk]);
                unsigned long long a1 = pack2(As[(ty * 2 + 1) * 17 + kk]);
                ulonglong2 bv = *(ulonglong2*)&Bs[kk * 64 + tx * 4];
                fma2(acc[0][0], a0, bv.x); fma2(acc[0][1], a0, bv.y);
                fma2(acc[1][0], a1, bv.x); fma2(acc[1][1], a1, bv.y);
            }
            __syncthreads();
        }
#pragma unroll
        for (int i = 0; i < 2; i++) {
            int b = b0 + ty * 2 + i;
            int c = c0 + tx * 4;
            float2 p0 = unpack2(acc[i][0]);
            float2 p1 = unpack2(acc[i][1]);
            float4 o;
            o.x = tanhf(p0.x + b_stk[c + 0]);
            o.y = tanhf(p0.y + b_stk[c + 1]);
            o.z = tanhf(p1.x + b_stk[c + 2]);
            o.w = tanhf(p1.y + b_stk[c + 3]);
            *(float4*)&pvout[b * (NSTACK * ELEM) + c] = o;
        }
        return;
    }

    if (blk < STACK_BASE) {
        // ---- ACT: act probs for step s ----
        if (s >= S_) return;
        int ab = blk - GRU_BLOCKS - AUX_BLOCKS;   // 0..31
        int b0 = ab * 16;
        const float* hin = g_h[s & 1];
        float* hsm = sm;                 // [16][257]
        float* logit = sm + 16 * 257;    // 96
        {
            int r = tid >> 4, c0 = (tid & 15) * 16;
#pragma unroll
            for (int q = 0; q < 4; q++) {
                float4 v = *(const float4*)&hin[(b0 + r) * H_ + c0 + q * 4];
                hsm[r * 257 + c0 + q * 4 + 0] = v.x;
                hsm[r * 257 + c0 + q * 4 + 1] = v.y;
                hsm[r * 257 + c0 + q * 4 + 2] = v.z;
                hsm[r * 257 + c0 + q * 4 + 3] = v.w;
            }
        }
        __syncthreads();
        if (tid < 96) {
            int bl = tid / 6, o = tid % 6;
            const float* wr = W_act + o * H_;
            float sum = b_act[o];
#pragma unroll 4
            for (int k = 0; k < H_; k++) sum += hsm[bl * 257 + k] * wr[k];
            logit[tid] = sum;
        }
        __syncthreads();
        if (tid < 32) {
            int bl = tid >> 1, n = tid & 1;
            float l0 = logit[bl * 6 + n * 3 + 0];
            float l1 = logit[bl * 6 + n * 3 + 1];
            float l2 = logit[bl * 6 + n * 3 + 2];
            float mx = fmaxf(l0, fmaxf(l1, l2));
            float e0 = expf(l0 - mx), e1 = expf(l1 - mx), e2 = expf(l2 - mx);
            float inv = 1.f / (e0 + e1 + e2);
            float* P = g_P[s & 1] + ((b0 + bl) * 2 + n) * 3;
            P[0] = e0 * inv; P[1] = e1 * inv; P[2] = e2 * inv;
        }
        return;
    }

    // ---- STACK update for step s-1, two stacks per block ----
    {
        if (s == 0) return;
        int b = blk - STACK_BASE;                 // 0..255?? -> 0..255 covers B/2... b in [0,256)
        // each block handles batches b and b+256? No: 256 blocks, each handles ONE b with n=0,1
        // STEP_BLOCKS allocates B_/2 = 256 blocks; map block -> 2 (b,n) pairs: b2 = block, n=0/1? That
        // covers only 256 of 512 batches. Instead: block covers batches 2*b and 2*b+1? Simpler:
        // block handles (b, n) pairs: (blkb, 0) and (blkb, 1) for blkb = b, and ALSO (b+256, 0/1)? 
        // -> handle batch pair: b and b + 256, one stack index each round: see loop below.
        int e = tid & 63;
        int rb = (tid >> 6) * 16;
        float emp = empty_elem[e];
#pragma unroll
        for (int half = 0; half < 2; half++) {
            int bb = b + half * 256;              // batches [0,256) then [256,512)
#pragma unroll
            for (int n = 0; n < 2; n++) {
                const float* P = g_P[(s - 1) & 1] + (bb * 2 + n) * 3;
                const float* pv = g_PV[(s - 1) & 1] + bb * (NSTACK * ELEM) + n * ELEM;
                float* gst = stacks + ((size_t)(bb * NSTACK + n) << 12);
                float r[18];
#pragma unroll
                for (int i = 0; i < 18; i++) {
                    int row = rb - 1 + i;
                    r[i] = (row >= 0 && row < SSIZE) ? gst[row * ELEM + e] : 0.f;
                }
                float ppush = P[0], ppop = P[1], pnoop = P[2];
                float pve = ppush * pv[e];
                __syncthreads();
#pragma unroll
                for (int i = 0; i < 16; i++) {
                    int row = rb + i;
                    float v;
                    if (row == 0)              v = pve;
                    else if (row == SSIZE - 1) v = emp;
                    else v = ppush * r[i] + ppop * r[i + 2] + pnoop * r[i + 1];
                    gst[row * ELEM + e] = v;
                }
                __syncthreads();
            }
        }
    }
}

// ---------------- softmax over S + weighted sum -> final_hidden ----------------
__global__ void __launch_bounds__(256) attn_final_k(const float* __restrict__ outputs,
                                                    const int* __restrict__ tokens,
                                                    const float* __restrict__ ba2,
                                                    float* __restrict__ fh) {
    int b = blockIdx.x;
    int tid = threadIdx.x;           // = s index / h index
    int lane = tid & 31, wid = tid >> 5;
    __shared__ float a_sm[S_];
    __shared__ float rmax[8];
    __shared__ float rsum[8];

    float v = g_spart[0][tid * B_ + b] + g_spart[1][tid * B_ + b] + ba2[0];
    if (tokens[tid * B_ + b] == 0) v = -1e30f;

    float m = v;
#pragma unroll
    for (int off = 16; off > 0; off >>= 1) m = fmaxf(m, __shfl_xor_sync(0xffffffffu, m, off));
    if (lane == 0) rmax[wid] = m;
    __syncthreads();
    float mx = rmax[0];
#pragma unroll
    for (int i = 1; i < 8; i++) mx = fmaxf(mx, rmax[i]);
    float e = expf(v - mx);
    float sum = e;
#pragma unroll
    for (int off = 16; off > 0; off >>= 1) sum += __shfl_xor_sync(0xffffffffu, sum, off);
    if (lane == 0) rsum[wid] = sum;
    __syncthreads();
    float tot = rsum[0];
#pragma unroll
    for (int i = 1; i < 8; i++) tot += rsum[i];
    a_sm[tid] = e / tot;
    __syncthreads();

    float acc = 0.f;
    for (int s2 = 0; s2 < S_; s2++)
        acc += a_sm[s2] * outputs[((size_t)s2 * B_ + b) * H_ + tid];
    fh[b * H_ + tid] = acc;
}

// ---------------- launch ----------------
extern "C" void kernel_launch(void* const* d_in, const int* in_sizes, int n_in,
                              void* d_out, int out_size) {
    const int*   tokens     = (const int*)d_in[0];
    const float* emb        = (const float*)d_in[1];
    const float* W_ih       = (const float*)d_in[2];
    const float* W_hh       = (const float*)d_in[3];
    const float* b_ih       = (const float*)d_in[4];
    const float* b_hh       = (const float*)d_in[5];
    const float* W_act      = (const float*)d_in[6];
    const float* b_act      = (const float*)d_in[7];
    const float* W_stk      = (const float*)d_in[8];
    const float* b_stk      = (const float*)d_in[9];
    const float* empty_elem = (const float*)d_in[10];
    // d_in[11] = W_up, d_in[12] = W_down : shift matrices, hardcoded
    const float* Wa1        = (const float*)d_in[13];
    const float* ba1        = (const float*)d_in[14];
    const float* Wa2        = (const float*)d_in[15];
    const float* ba2        = (const float*)d_in[16];

    float* out     = (float*)d_out;
    float* outputs = out;
    float* fh      = out + (size_t)S_ * B_ * H_;
    float* stacks  = fh + (size_t)B_ * H_;

    float *pWihT, *pWa1T, *pEMB;
    cudaGetSymbolAddress((void**)&pWihT, g_WihT);
    cudaGetSymbolAddress((void**)&pWa1T, g_Wa1T);
    cudaGetSymbolAddress((void**)&pEMB,  g_EMB_GI);

    // launch 0: all prep
    prep_k<<<(B_ * NSTACK * SSIZE * ELEM + 255) / 256, 256>>>(
        W_ih, W_hh, W_stk, Wa1, empty_elem, stacks);

    // launch 1: EMB_GI = emb @ W_ih^T + b_ih  (32000 x 768)
    {
        dim3 grid(H3 / 128, VOCAB_ / 128);
        sgemm128_k<false><<<grid, 256>>>(emb, pWihT, b_ih, pEMB, nullptr, VOCAB_, H3, H_);
    }

    // launches 2..258: recurrence (launch 5 = step s=3, gets profiled by ncu)
    for (int s = 0; s <= S_; s++) {
        step_kernel<<<STEP_BLOCKS, 256>>>(s, tokens, b_ih, b_hh, W_act, b_act,
                                          b_stk, empty_elem, outputs, stacks);
    }

    // attention: fused tanh(outputs@Wa1^T+ba1)@Wa2^T partials
    {
        dim3 grid(H_ / 128, (S_ * B_) / 128);
        sgemm128_k<true><<<grid, 256>>>(outputs, pWa1T, ba1, nullptr, Wa2, S_ * B_, H_, H_);
    }
    attn_final_k<<<B_, 256>>>(outputs, tokens, ba2, fh);
}

// round 4
// speedup vs baseline: 1.3694x; 1.3694x over previous
#include <cuda_runtime.h>
#include <math.h>

#define S_ 256
#define B_ 512
#define H_ 256
#define H3 768
#define VOCAB_ 32000
#define NSTACK 2
#define SSIZE 64
#define ELEM 64
#define NBLK 256

// ---------------- device scratch (static, no allocation) ----------------
__device__ float g_EMB_GI[VOCAB_ * H3];       // emb @ W_ih^T + b_ih
__device__ float g_WihT[H_ * H3];             // [k][n]
__device__ float g_WhhT[H_ * H3];             // [k][n]
__device__ float g_WstkT[H_ * (NSTACK * ELEM)];
__device__ float g_Wa1T[H_ * H_];
__device__ float g_h[2][B_ * H_];             // hidden ping-pong
__device__ float g_PV[2][B_ * NSTACK * ELEM]; // push_vals ping-pong
__device__ float g_P[2][B_ * NSTACK * 3];     // act probs ping-pong
__device__ float g_spart[2][S_ * B_];         // attention score partials
__device__ unsigned int g_bar;                // grid barrier counter

__device__ __forceinline__ float sigmoidf_(float x) { return 1.f / (1.f + expf(-x)); }

// ---------------- packed f32x2 helpers ----------------
__device__ __forceinline__ unsigned long long pack2(float x) {
    unsigned long long d;
    unsigned int u = __float_as_uint(x);
    asm("mov.b64 %0, {%1, %1};" : "=l"(d) : "r"(u));
    return d;
}
__device__ __forceinline__ void fma2(unsigned long long& d, unsigned long long a,
                                     unsigned long long b) {
    asm("fma.rn.f32x2 %0, %1, %2, %0;" : "+l"(d) : "l"(a), "l"(b));
}
__device__ __forceinline__ float2 unpack2(unsigned long long v) {
    unsigned int lo, hi;
    asm("mov.b64 {%0, %1}, %2;" : "=r"(lo), "=r"(hi) : "l"(v));
    return make_float2(__uint_as_float(lo), __uint_as_float(hi));
}

// ---------------- prep kernels (split so persist = launch #5 for ncu) ----------------
__global__ void prep_a(const float* __restrict__ W_ih) {
    int idx = blockIdx.x * 256 + threadIdx.x;
    if (idx < H3 * H_) { int r = idx % H3, c = idx / H3; g_WihT[idx] = W_ih[r * H_ + c]; }
}
__global__ void prep_b(const float* __restrict__ W_hh) {
    int idx = blockIdx.x * 256 + threadIdx.x;
    if (idx < H3 * H_) { int r = idx % H3, c = idx / H3; g_WhhT[idx] = W_hh[r * H_ + c]; }
}
__global__ void prep_c(const float* __restrict__ W_stk, const float* __restrict__ Wa1) {
    int idx = blockIdx.x * 256 + threadIdx.x;
    if (idx < (NSTACK * ELEM) * H_) {
        int r = idx % (NSTACK * ELEM), c = idx / (NSTACK * ELEM);
        g_WstkT[idx] = W_stk[r * H_ + c];
    }
    if (idx < H_ * H_) { int r = idx % H_, c = idx / H_; g_Wa1T[idx] = Wa1[r * H_ + c]; }
}
__global__ void prep_d() {
    int idx = blockIdx.x * 256 + threadIdx.x;
    if (idx < B_ * H_) g_h[0][idx] = 0.f;
    if (idx == 0) g_bar = 0u;
}

// ---------------- 128x128x16 SGEMM with f32x2 ----------------
template <bool SCORE>
__global__ void __launch_bounds__(256) sgemm128_k(
    const float* __restrict__ A, const float* __restrict__ Bm,
    const float* __restrict__ bias, float* __restrict__ C,
    const float* __restrict__ Wa2,
    int M, int N, int K)
{
    __shared__ __align__(16) float As[16][128];   // [k][m]
    __shared__ __align__(16) float Bs[16][128];   // [k][n]
    int tid = threadIdx.x;
    int m0 = blockIdx.y * 128, n0 = blockIdx.x * 128;
    int tx = tid & 15, ty = tid >> 4;

    unsigned long long acc[2][2][4][2];
#pragma unroll
    for (int a = 0; a < 2; a++)
#pragma unroll
        for (int b = 0; b < 2; b++)
#pragma unroll
            for (int c = 0; c < 4; c++) { acc[a][b][c][0] = 0ull; acc[a][b][c][1] = 0ull; }

    for (int k0 = 0; k0 < K; k0 += 16) {
#pragma unroll
        for (int i = 0; i < 2; i++) {
            int f = tid * 2 + i;
            int arow = f >> 2, aq = (f & 3) * 4;
            float4 v = *(const float4*)&A[(size_t)(m0 + arow) * K + k0 + aq];
            As[aq + 0][arow] = v.x; As[aq + 1][arow] = v.y;
            As[aq + 2][arow] = v.z; As[aq + 3][arow] = v.w;
            int brow = f >> 5, bc = (f & 31) * 4;
            *(float4*)&Bs[brow][bc] = *(const float4*)&Bm[(size_t)(k0 + brow) * N + n0 + bc];
        }
        __syncthreads();
#pragma unroll
        for (int kk = 0; kk < 16; kk++) {
            float4 a0 = *(float4*)&As[kk][ty * 4];
            float4 a1 = *(float4*)&As[kk][ty * 4 + 64];
            unsigned long long ap[2][4];
            ap[0][0] = pack2(a0.x); ap[0][1] = pack2(a0.y);
            ap[0][2] = pack2(a0.z); ap[0][3] = pack2(a0.w);
            ap[1][0] = pack2(a1.x); ap[1][1] = pack2(a1.y);
            ap[1][2] = pack2(a1.z); ap[1][3] = pack2(a1.w);
            ulonglong2 b0 = *(ulonglong2*)&Bs[kk][tx * 4];
            ulonglong2 b1 = *(ulonglong2*)&Bs[kk][tx * 4 + 64];
#pragma unroll
            for (int ic = 0; ic < 2; ic++)
#pragma unroll
                for (int i = 0; i < 4; i++) {
                    fma2(acc[ic][0][i][0], ap[ic][i], b0.x);
                    fma2(acc[ic][0][i][1], ap[ic][i], b0.y);
                    fma2(acc[ic][1][i][0], ap[ic][i], b1.x);
                    fma2(acc[ic][1][i][1], ap[ic][i], b1.y);
                }
        }
        __syncthreads();
    }

    if (!SCORE) {
#pragma unroll
        for (int ic = 0; ic < 2; ic++)
#pragma unroll
            for (int i = 0; i < 4; i++) {
                int m = m0 + ic * 64 + ty * 4 + i;
#pragma unroll
                for (int jc = 0; jc < 2; jc++) {
                    int n = n0 + jc * 64 + tx * 4;
                    float2 p0 = unpack2(acc[ic][jc][i][0]);
                    float2 p1 = unpack2(acc[ic][jc][i][1]);
                    float4 o;
                    o.x = p0.x + bias[n + 0];
                    o.y = p0.y + bias[n + 1];
                    o.z = p1.x + bias[n + 2];
                    o.w = p1.y + bias[n + 3];
                    *(float4*)&C[(size_t)m * N + n] = o;
                }
            }
    } else {
        float4 bb[2], ww[2];
#pragma unroll
        for (int jc = 0; jc < 2; jc++) {
            int n = n0 + jc * 64 + tx * 4;
            bb[jc] = *(const float4*)&bias[n];
            ww[jc] = *(const float4*)&Wa2[n];
        }
#pragma unroll
        for (int ic = 0; ic < 2; ic++)
#pragma unroll
            for (int i = 0; i < 4; i++) {
                float p = 0.f;
#pragma unroll
                for (int jc = 0; jc < 2; jc++) {
                    float2 p0 = unpack2(acc[ic][jc][i][0]);
                    float2 p1 = unpack2(acc[ic][jc][i][1]);
                    p += tanhf(p0.x + bb[jc].x) * ww[jc].x;
                    p += tanhf(p0.y + bb[jc].y) * ww[jc].y;
                    p += tanhf(p1.x + bb[jc].z) * ww[jc].z;
                    p += tanhf(p1.y + bb[jc].w) * ww[jc].w;
                }
#pragma unroll
                for (int off = 8; off > 0; off >>= 1)
                    p += __shfl_xor_sync(0xffffffffu, p, off);
                if (tx == 0) {
                    int m = m0 + ic * 64 + ty * 4 + i;
                    g_spart[blockIdx.x][m] = p;
                }
            }
    }
}

// ---------------- persistent recurrence kernel ----------------
// 256 blocks x 256 threads, all co-resident (2/SM). Grid barrier per step.
// blocks [0,128):   GRU tile: 16 batches x 64 h-cols x 3 gates
// blocks [128,256): AUX tile: 8 batches x 64 pv-cols; jt==0 also ACT (probs)
// every block owns 4 stacks in SMEM for the whole recurrence.
// SMEM: stacks 65536B | GRU: As 32*18*4=2304B, Bs 3*32*68*4=26112B (AUX aliases)
#define SMEM_DYN (65536 + 2304 + 26112)

__global__ void __launch_bounds__(256, 2) persist_k(
    const int* __restrict__ tokens,
    const float* __restrict__ b_ih,
    const float* __restrict__ b_hh,
    const float* __restrict__ W_act,
    const float* __restrict__ b_act,
    const float* __restrict__ b_stk,
    const float* __restrict__ empty_elem,
    float* __restrict__ outputs,
    float* __restrict__ stacks_out)
{
    extern __shared__ __align__(16) float smem[];
    float* stk = smem;                 // 4 * 4096
    float* gA  = smem + 16384;         // [k(32)][m(16)+pad2]
    float* gB  = gA + 32 * 18;         // [3][32][64+pad4]
    float* aA  = gA;                   // [k(32)][m(8)+pad2]
    float* aB  = aA + 320;             // [32][64+pad4]
    float* lg  = aB + 32 * 68;         // 48 logits

    int tid = threadIdx.x;
    int blk = blockIdx.x;
    int e   = tid & 63;
    int qr  = (tid >> 6) * 16;
    int tx  = tid & 31, ty = tid >> 5;
    float emp = empty_elem[e];

    // init this block's 4 stacks to empty
    for (int i = tid; i < 4 * 4096; i += 256) stk[i] = empty_elem[i & 63];

    const bool isGRU = blk < 128;
    int mt = blk >> 2, jt = blk & 3;          // GRU mapping
    int ai = blk - 128, amt = ai >> 1, ajt = ai & 1;  // AUX mapping

    for (int s = 0; s < S_; s++) {
        // ---- stack update for step s-1 (SMEM-resident) ----
        if (s > 0) {
            int ph = (s - 1) & 1;
#pragma unroll
            for (int st = 0; st < 4; st++) {
                int sid = blk * 4 + st;
                int b = sid >> 1, n = sid & 1;
                float pp  = __ldcg(&g_P[ph][sid * 3 + 0]);
                float po  = __ldcg(&g_P[ph][sid * 3 + 1]);
                float pn  = __ldcg(&g_P[ph][sid * 3 + 2]);
                float pvv = __ldcg(&g_PV[ph][b * (NSTACK * ELEM) + n * ELEM + e]);
                float* Sm = stk + st * 4096;
                float r[18];
#pragma unroll
                for (int i = 0; i < 18; i++) {
                    int row = qr - 1 + i;
                    r[i] = (row >= 0 && row < SSIZE) ? Sm[row * 64 + e] : 0.f;
                }
                __syncthreads();
#pragma unroll
                for (int i = 0; i < 16; i++) {
                    int row = qr + i;
                    float v;
                    if (row == 0)              v = pp * pvv;
                    else if (row == SSIZE - 1) v = emp;
                    else v = fmaf(pp, r[i], fmaf(po, r[i + 2], pn * r[i + 1]));
                    Sm[row * 64 + e] = v;
                }
                __syncthreads();
            }
        }

        const float* hin = g_h[s & 1];
        if (isGRU) {
            float* hout = g_h[(s + 1) & 1];
            int b0 = mt * 16, j0 = jt * 64;
            unsigned long long acc[3][2] = {{0ull,0ull},{0ull,0ull},{0ull,0ull}};
            for (int k0 = 0; k0 < H_; k0 += 32) {
                {   int m = tid >> 4, k2 = (tid & 15) * 2;
                    float2 v = __ldcg((const float2*)&hin[(b0 + m) * H_ + k0 + k2]);
                    gA[k2 * 18 + m] = v.x; gA[(k2 + 1) * 18 + m] = v.y; }
                {   int rI = tid >> 3, c = (tid & 7) * 8;
                    const float* src = &g_WhhT[(size_t)(k0 + rI) * H3 + j0 + c];
#pragma unroll
                    for (int g = 0; g < 3; g++) {
                        *(float4*)&gB[(g * 32 + rI) * 68 + c]     = *(const float4*)(src + g * H_);
                        *(float4*)&gB[(g * 32 + rI) * 68 + c + 4] = *(const float4*)(src + g * H_ + 4);
                    }
                }
                __syncthreads();
#pragma unroll
                for (int kk = 0; kk < 32; kk++) {
                    float2 av = *(float2*)&gA[kk * 18 + ty * 2];
                    unsigned long long a0 = pack2(av.x), a1 = pack2(av.y);
#pragma unroll
                    for (int g = 0; g < 3; g++) {
                        unsigned long long bv = *(unsigned long long*)&gB[(g * 32 + kk) * 68 + tx * 2];
                        fma2(acc[g][0], a0, bv);
                        fma2(acc[g][1], a1, bv);
                    }
                }
                __syncthreads();
            }
            int j = j0 + tx * 2;
            float2 br = *(const float2*)&b_hh[j];
            float2 bz = *(const float2*)&b_hh[H_ + j];
            float2 bn = *(const float2*)&b_hh[2 * H_ + j];
#pragma unroll
            for (int mi = 0; mi < 2; mi++) {
                int b = b0 + ty * 2 + mi;
                int tok = tokens[s * B_ + b];
                const float* gi = (tok == 0) ? b_ih : (g_EMB_GI + (size_t)tok * H3);
                float2 gr = *(const float2*)&gi[j];
                float2 gz = *(const float2*)&gi[H_ + j];
                float2 gn = *(const float2*)&gi[2 * H_ + j];
                float2 hp = __ldcg((const float2*)&hin[b * H_ + j]);
                float2 R = unpack2(acc[0][mi]);
                float2 Z = unpack2(acc[1][mi]);
                float2 N = unpack2(acc[2][mi]);
                float2 o;
                {   float rr = sigmoidf_(gr.x + R.x + br.x);
                    float zz = sigmoidf_(gz.x + Z.x + bz.x);
                    float nn = tanhf(gn.x + rr * (N.x + bn.x));
                    o.x = (1.f - zz) * nn + zz * hp.x; }
                {   float rr = sigmoidf_(gr.y + R.y + br.y);
                    float zz = sigmoidf_(gz.y + Z.y + bz.y);
                    float nn = tanhf(gn.y + rr * (N.y + bn.y));
                    o.y = (1.f - zz) * nn + zz * hp.y; }
                *(float2*)&hout[b * H_ + j] = o;
                *(float2*)&outputs[((size_t)s * B_ + b) * H_ + j] = o;
            }
        } else {
            int b0 = amt * 8, c0 = ajt * 64;
            unsigned long long acc = 0ull;
            float asum = 0.f;
            bool act = (ajt == 0) && (tid < 48);
            int abl = tid / 6, ao = tid % 6;
            for (int k0 = 0; k0 < H_; k0 += 32) {
                {   int m = tid >> 5, kk = tid & 31;
                    aA[kk * 10 + m] = __ldcg(&hin[(b0 + m) * H_ + k0 + kk]); }
                {   int rI = tid >> 3, c = (tid & 7) * 8;
                    const float* src = &g_WstkT[(size_t)(k0 + rI) * (NSTACK * ELEM) + c0 + c];
                    *(float4*)&aB[rI * 68 + c]     = *(const float4*)(src);
                    *(float4*)&aB[rI * 68 + c + 4] = *(const float4*)(src + 4);
                }
                __syncthreads();
#pragma unroll
                for (int kk = 0; kk < 32; kk++) {
                    unsigned long long ap = pack2(aA[kk * 10 + ty]);
                    unsigned long long bv = *(unsigned long long*)&aB[kk * 68 + tx * 2];
                    fma2(acc, ap, bv);
                }
                if (act) {
#pragma unroll 8
                    for (int kk = 0; kk < 32; kk++)
                        asum = fmaf(aA[kk * 10 + abl], W_act[ao * H_ + k0 + kk], asum);
                }
                __syncthreads();
            }
            {   int b = b0 + ty;
                int c = c0 + tx * 2;
                float2 p = unpack2(acc);
                float2 o;
                o.x = tanhf(p.x + b_stk[c]);
                o.y = tanhf(p.y + b_stk[c + 1]);
                *(float2*)&g_PV[s & 1][b * (NSTACK * ELEM) + c] = o; }
            if (ajt == 0) {
                if (tid < 48) lg[tid] = asum + b_act[ao];
                __syncthreads();
                if (tid < 16) {
                    int bl = tid >> 1, n = tid & 1;
                    float l0 = lg[bl * 6 + n * 3 + 0];
                    float l1 = lg[bl * 6 + n * 3 + 1];
                    float l2 = lg[bl * 6 + n * 3 + 2];
                    float mx = fmaxf(l0, fmaxf(l1, l2));
                    float e0 = expf(l0 - mx), e1 = expf(l1 - mx), e2 = expf(l2 - mx);
                    float inv = 1.f / (e0 + e1 + e2);
                    int sid = (b0 + bl) * 2 + n;
                    g_P[s & 1][sid * 3 + 0] = e0 * inv;
                    g_P[s & 1][sid * 3 + 1] = e1 * inv;
                    g_P[s & 1][sid * 3 + 2] = e2 * inv;
                }
            }
        }

        // ---- grid barrier ----
        __threadfence();
        __syncthreads();
        if (tid == 0) {
            atomicAdd(&g_bar, 1u);
            unsigned int target = (unsigned int)NBLK * (unsigned int)(s + 1);
            while (*((volatile unsigned int*)&g_bar) < target) { }
        }
        __syncthreads();
    }

    // ---- final stack update (step S-1) + write out ----
    {
        int ph = (S_ - 1) & 1;
#pragma unroll
        for (int st = 0; st < 4; st++) {
            int sid = blk * 4 + st;
            int b = sid >> 1, n = sid & 1;
            float pp  = __ldcg(&g_P[ph][sid * 3 + 0]);
            float po  = __ldcg(&g_P[ph][sid * 3 + 1]);
            float pn  = __ldcg(&g_P[ph][sid * 3 + 2]);
            float pvv = __ldcg(&g_PV[ph][b * (NSTACK * ELEM) + n * ELEM + e]);
            float* Sm = stk + st * 4096;
            float* dst = stacks_out + (size_t)sid * 4096;
            float r[18];
#pragma unroll
            for (int i = 0; i < 18; i++) {
                int row = qr - 1 + i;
                r[i] = (row >= 0 && row < SSIZE) ? Sm[row * 64 + e] : 0.f;
            }
#pragma unroll
            for (int i = 0; i < 16; i++) {
                int row = qr + i;
                float v;
                if (row == 0)              v = pp * pvv;
                else if (row == SSIZE - 1) v = emp;
                else v = fmaf(pp, r[i], fmaf(po, r[i + 2], pn * r[i + 1]));
                dst[row * 64 + e] = v;
            }
        }
    }
}

// ---------------- softmax over S + weighted sum -> final_hidden ----------------
__global__ void __launch_bounds__(256) attn_final_k(const float* __restrict__ outputs,
                                                    const int* __restrict__ tokens,
                                                    const float* __restrict__ ba2,
                                                    float* __restrict__ fh) {
    int b = blockIdx.x;
    int tid = threadIdx.x;
    int lane = tid & 31, wid = tid >> 5;
    __shared__ float a_sm[S_];
    __shared__ float rmax[8];
    __shared__ float rsum[8];

    float v = g_spart[0][tid * B_ + b] + g_spart[1][tid * B_ + b] + ba2[0];
    if (tokens[tid * B_ + b] == 0) v = -1e30f;

    float m = v;
#pragma unroll
    for (int off = 16; off > 0; off >>= 1) m = fmaxf(m, __shfl_xor_sync(0xffffffffu, m, off));
    if (lane == 0) rmax[wid] = m;
    __syncthreads();
    float mx = rmax[0];
#pragma unroll
    for (int i = 1; i < 8; i++) mx = fmaxf(mx, rmax[i]);
    float e = expf(v - mx);
    float sum = e;
#pragma unroll
    for (int off = 16; off > 0; off >>= 1) sum += __shfl_xor_sync(0xffffffffu, sum, off);
    if (lane == 0) rsum[wid] = sum;
    __syncthreads();
    float tot = rsum[0];
#pragma unroll
    for (int i = 1; i < 8; i++) tot += rsum[i];
    a_sm[tid] = e / tot;
    __syncthreads();

    float acc = 0.f;
    for (int s2 = 0; s2 < S_; s2++)
        acc += a_sm[s2] * outputs[((size_t)s2 * B_ + b) * H_ + tid];
    fh[b * H_ + tid] = acc;
}

// ---------------- launch ----------------
extern "C" void kernel_launch(void* const* d_in, const int* in_sizes, int n_in,
                              void* d_out, int out_size) {
    const int*   tokens     = (const int*)d_in[0];
    const float* emb        = (const float*)d_in[1];
    const float* W_ih       = (const float*)d_in[2];
    const float* W_hh       = (const float*)d_in[3];
    const float* b_ih       = (const float*)d_in[4];
    const float* b_hh       = (const float*)d_in[5];
    const float* W_act      = (const float*)d_in[6];
    const float* b_act      = (const float*)d_in[7];
    const float* W_stk      = (const float*)d_in[8];
    const float* b_stk      = (const float*)d_in[9];
    const float* empty_elem = (const float*)d_in[10];
    // d_in[11] = W_up, d_in[12] = W_down : shift matrices, hardcoded
    const float* Wa1        = (const float*)d_in[13];
    const float* ba1        = (const float*)d_in[14];
    const float* Wa2        = (const float*)d_in[15];
    const float* ba2        = (const float*)d_in[16];

    float* out     = (float*)d_out;
    float* outputs = out;
    float* fh      = out + (size_t)S_ * B_ * H_;
    float* stacks  = fh + (size_t)B_ * H_;

    float *pWihT, *pWa1T, *pEMB;
    cudaGetSymbolAddress((void**)&pWihT, g_WihT);
    cudaGetSymbolAddress((void**)&pWa1T, g_Wa1T);
    cudaGetSymbolAddress((void**)&pEMB,  g_EMB_GI);

    static int smem_set = 0;
    if (!smem_set) {
        cudaFuncSetAttribute(persist_k, cudaFuncAttributeMaxDynamicSharedMemorySize, SMEM_DYN);
        smem_set = 1;
    }

    // launches 0-3: prep
    prep_a<<<(H3 * H_ + 255) / 256, 256>>>(W_ih);
    prep_b<<<(H3 * H_ + 255) / 256, 256>>>(W_hh);
    prep_c<<<(H_ * H_ + 255) / 256, 256>>>(W_stk, Wa1);
    prep_d<<<(B_ * H_ + 255) / 256, 256>>>();

    // launch 4: EMB_GI = emb @ W_ih^T + b_ih  (32000 x 768)
    {
        dim3 grid(H3 / 128, VOCAB_ / 128);
        sgemm128_k<false><<<grid, 256>>>(emb, pWihT, b_ih, pEMB, nullptr, VOCAB_, H3, H_);
    }

    // launch 5: the whole recurrence in ONE persistent kernel
    persist_k<<<NBLK, 256, SMEM_DYN>>>(tokens, b_ih, b_hh, W_act, b_act, b_stk,
                                       empty_elem, outputs, stacks);

    // launch 6: attention partials (fused tanh(outputs@Wa1^T+ba1)@Wa2^T)
    {
        dim3 grid(H_ / 128, (S_ * B_) / 128);
        sgemm128_k<true><<<grid, 256>>>(outputs, pWa1T, ba1, nullptr, Wa2, S_ * B_, H_, H_);
    }
    // launch 7: softmax + weighted sum
    attn_final_k<<<B_, 256>>>(outputs, tokens, ba2, fh);
}